// round 7
// baseline (speedup 1.0000x reference)
#include <cuda_runtime.h>
#include <cuda_fp16.h>
#include <cstdint>
#include <math.h>

// Problem constants (LinearAttention_22943715295778)
#define PB 4
#define PN 8192
#define PM 2048
#define PC 512
#define PL 256
#define PH 8
#define DL 32   // L/H
#define DC 64   // C/H
#define EPS 1e-6f

#define NACC (PB*PH*DC*DL + PB*PH*DL)             // 66560

// -------- device-global scratch (allocation-free requirement) --------
__device__ __half g_kt[PB * PH * DL * PN];        // 16 MB : k^T [bh][d][n], fp16, post-elu
__device__ __half g_vt[PB * PH * DC * PN];        // 32 MB : v^T [bh][c][n], fp16
__device__ __half g_qp[PB * PM * PL];             //  4 MB : q [row][256], fp16, post-elu
__device__ float  g_acc[NACC];                    // kv (65536) + ksum (1024)
__device__ __half g_xh[PB * PN * PC];             // 32 MB : input_tokens fp16
__device__ __half g_qh[PB * PM * PC];             //  8 MB : query_tokens fp16
__device__ __half g_wth[1024 * PC];               // rows: [WkT 256][WvT 512][WqT 256], fp16
__device__ float  g_bias[1024];                   // [bk | bv | bq]

// ===================== helpers =====================
__device__ __forceinline__ uint32_t smem_u32(const void* p) {
    uint32_t a;
    asm("{ .reg .u64 t; cvta.to.shared.u64 t, %1; cvt.u32.u64 %0, t; }"
        : "=r"(a) : "l"(p));
    return a;
}

// ===================== prep: weight transposes + bias + zero =====================
__global__ __launch_bounds__(256) void prep_kernel(
    const float* __restrict__ Wk, const float* __restrict__ Wv,
    const float* __restrict__ Wq,
    const float* __restrict__ bk, const float* __restrict__ bv,
    const float* __restrict__ bq)
{
    __shared__ float tile[32][33];
    const int n0 = blockIdx.x * 32, k0 = blockIdx.y * 32;
    const float *W, *bsrc; int N, ns;
    if (n0 < 256)      { W = Wk; bsrc = bk; N = PL; ns = n0; }
    else if (n0 < 768) { W = Wv; bsrc = bv; N = PC; ns = n0 - 256; }
    else               { W = Wq; bsrc = bq; N = PL; ns = n0 - 768; }
    const int tx = threadIdx.x, ty = threadIdx.y;
    for (int i = ty; i < 32; i += 8)
        tile[i][tx] = W[(size_t)(k0 + i) * N + ns + tx];
    __syncthreads();
    for (int i = ty; i < 32; i += 8)
        g_wth[(size_t)(n0 + i) * PC + k0 + tx] = __float2half_rn(tile[tx][i]);
    if (blockIdx.y == 0 && ty == 0)
        g_bias[n0 + tx] = bsrc[ns + tx];
    if (blockIdx.y == 1) {
        int t = ty * 32 + tx;
#pragma unroll
        for (int i = 0; i < 9; i++) {
            int j = blockIdx.x * 256 + t + i * 8192;
            if (j < NACC) g_acc[j] = 0.0f;
        }
    }
}

// ===================== fp16 conversion of X and Q =====================
__global__ __launch_bounds__(256) void convert_kernel(
    const float* __restrict__ X, const float* __restrict__ Q)
{
    const int nx = PB * PN * PC / 4;   // float4 count
    const int nq = PB * PM * PC / 4;
    int i = blockIdx.x * blockDim.x + threadIdx.x;
    if (i < nx) {
        float4 v = ((const float4*)X)[i];
        __half2* d = (__half2*)g_xh;
        d[2 * i]     = __floats2half2_rn(v.x, v.y);
        d[2 * i + 1] = __floats2half2_rn(v.z, v.w);
    } else if (i < nx + nq) {
        int j = i - nx;
        float4 v = ((const float4*)Q)[j];
        __half2* d = (__half2*)g_qh;
        d[2 * j]     = __floats2half2_rn(v.x, v.y);
        d[2 * j + 1] = __floats2half2_rn(v.z, v.w);
    }
}

// ===================== fp16 mma mainloop (shared) =====================
#define TMm 128
#define TNn 128
#define BKh 64
#define SWORD 40                      // uint32 words per row (64 fp16 + pad)
#define TILEW (128 * SWORD)
#define NCHh (PC / BKh)               // 8
#define SMEM_GEMM (4 * TILEW * 4)     // 81920 bytes

__device__ __forceinline__ void mma_tile_loop_h(
    const __half* __restrict__ Ag0,
    const __half* __restrict__ Bg0,
    uint32_t* sm, int t, float acc[2][8][4])
{
    uint32_t* As = sm;
    uint32_t* Bs = sm + 2 * TILEW;
    const int wid = t >> 5, lane = t & 31;
    const int lr = lane >> 2, lc = lane & 3;
    const int wm = (wid & 3) * 32, wn = (wid >> 2) * 64;

    auto stage = [&](int c, int buf) {
        const __half* Ag = Ag0 + c * BKh;
        const __half* Bg = Bg0 + c * BKh;
        uint32_t* Ad = As + buf * TILEW;
        uint32_t* Bd = Bs + buf * TILEW;
#pragma unroll
        for (int i = 0; i < 4; i++) {
            int idx = i * 256 + t;
            int r = idx >> 3, seg = idx & 7;
            asm volatile("cp.async.cg.shared.global [%0], [%1], 16;"
                :: "r"(smem_u32(Ad + r * SWORD + seg * 4)),
                   "l"(Ag + (size_t)r * PC + seg * 8));
            asm volatile("cp.async.cg.shared.global [%0], [%1], 16;"
                :: "r"(smem_u32(Bd + r * SWORD + seg * 4)),
                   "l"(Bg + (size_t)r * PC + seg * 8));
        }
        asm volatile("cp.async.commit_group;" ::: "memory");
    };

    auto compute = [&](int buf) {
        const uint32_t* Ab = As + buf * TILEW;
        const uint32_t* Bb = Bs + buf * TILEW;
#pragma unroll
        for (int j = 0; j < 4; j++) {
            const int ko = 8 * j + 2 * lc;
            uint32_t af[2][4], bf[8][2];
#pragma unroll
            for (int mi = 0; mi < 2; mi++) {
                uint2 lo = *(const uint2*)&Ab[(wm + mi * 16 + lr) * SWORD + ko];
                uint2 hi = *(const uint2*)&Ab[(wm + mi * 16 + lr + 8) * SWORD + ko];
                af[mi][0] = lo.x; af[mi][1] = hi.x;
                af[mi][2] = lo.y; af[mi][3] = hi.y;
            }
#pragma unroll
            for (int ni = 0; ni < 8; ni++) {
                uint2 b = *(const uint2*)&Bb[(wn + ni * 8 + lr) * SWORD + ko];
                bf[ni][0] = b.x; bf[ni][1] = b.y;
            }
#pragma unroll
            for (int mi = 0; mi < 2; mi++)
#pragma unroll
                for (int ni = 0; ni < 8; ni++)
                    asm volatile(
                        "mma.sync.aligned.m16n8k16.row.col.f32.f16.f16.f32 "
                        "{%0,%1,%2,%3}, {%4,%5,%6,%7}, {%8,%9}, {%0,%1,%2,%3};"
                        : "+f"(acc[mi][ni][0]), "+f"(acc[mi][ni][1]),
                          "+f"(acc[mi][ni][2]), "+f"(acc[mi][ni][3])
                        : "r"(af[mi][0]), "r"(af[mi][1]),
                          "r"(af[mi][2]), "r"(af[mi][3]),
                          "r"(bf[ni][0]), "r"(bf[ni][1]));
        }
    };

    stage(0, 0);
    for (int c = 0; c < NCHh; c++) {
        if (c + 1 < NCHh) {
            stage(c + 1, (c + 1) & 1);
            asm volatile("cp.async.wait_group 1;" ::: "memory");
        } else {
            asm volatile("cp.async.wait_group 0;" ::: "memory");
        }
        __syncthreads();
        compute(c & 1);
        __syncthreads();
    }
}

// ===================== combined k|v|q projection GEMM =====================
// grid (8, 256). col0<768: kv projection (X rows, transposed fp16 out).
// col0>=768: q projection (Q rows, only blockIdx.y<64; fp16 row-major out).
#define TSTR 136   // fp16 stride of transpose buffer rows

__global__ __launch_bounds__(256, 2) void kvq_gemm_kernel()
{
    const int row0 = blockIdx.y * TMm;
    const int col0 = blockIdx.x * TNn;
    const bool isq = (col0 >= 768);
    if (isq && row0 >= PB * PM) return;

    extern __shared__ uint32_t smw[];
    const int t = threadIdx.x;

    float acc[2][8][4];
#pragma unroll
    for (int mi = 0; mi < 2; mi++)
#pragma unroll
        for (int ni = 0; ni < 8; ni++)
#pragma unroll
            for (int j = 0; j < 4; j++) acc[mi][ni][j] = 0.0f;

    const __half* Ag0 = isq ? (g_qh + (size_t)row0 * PC)
                            : (g_xh + (size_t)row0 * PC);
    mma_tile_loop_h(Ag0, g_wth + (size_t)col0 * PC, smw, t, acc);
    // ends with __syncthreads(); smem reusable.

    const int wid = t >> 5, lane = t & 31, lr = lane >> 2, lc = lane & 3;
    const int wm = (wid & 3) * 32, wn = (wid >> 2) * 64;
    const bool elu = (col0 < 256) || isq;

    if (isq) {
        // q: direct fp16 row-major stores to g_qp [8192][256]
#pragma unroll
        for (int mi = 0; mi < 2; mi++)
#pragma unroll
            for (int ni = 0; ni < 8; ni++) {
                int r  = row0 + wm + mi * 16 + lr;
                int cc = (col0 - 768) + wn + ni * 8 + 2 * lc;
                float b0 = g_bias[col0 + wn + ni * 8 + 2 * lc];
                float b1 = g_bias[col0 + wn + ni * 8 + 2 * lc + 1];
                float x0 = acc[mi][ni][0] + b0;
                float x1 = acc[mi][ni][1] + b1;
                float x2 = acc[mi][ni][2] + b0;
                float x3 = acc[mi][ni][3] + b1;
                x0 = x0 > 0.0f ? x0 + 1.0f : expf(x0);
                x1 = x1 > 0.0f ? x1 + 1.0f : expf(x1);
                x2 = x2 > 0.0f ? x2 + 1.0f : expf(x2);
                x3 = x3 > 0.0f ? x3 + 1.0f : expf(x3);
                *(__half2*)&g_qp[(size_t)r * PL + cc] =
                    __floats2half2_rn(x0, x1);
                *(__half2*)&g_qp[(size_t)(r + 8) * PL + cc] =
                    __floats2half2_rn(x2, x3);
            }
        return;
    }

    __half* st = (__half*)smw;   // [128 cols][TSTR]
#pragma unroll
    for (int mi = 0; mi < 2; mi++)
#pragma unroll
        for (int ni = 0; ni < 8; ni++) {
            int r  = wm + mi * 16 + lr;
            int cc = wn + ni * 8 + 2 * lc;
            float b0 = g_bias[col0 + cc], b1 = g_bias[col0 + cc + 1];
            float x0 = acc[mi][ni][0] + b0;
            float x1 = acc[mi][ni][1] + b1;
            float x2 = acc[mi][ni][2] + b0;
            float x3 = acc[mi][ni][3] + b1;
            if (elu) {
                x0 = x0 > 0.0f ? x0 + 1.0f : expf(x0);
                x1 = x1 > 0.0f ? x1 + 1.0f : expf(x1);
                x2 = x2 > 0.0f ? x2 + 1.0f : expf(x2);
                x3 = x3 > 0.0f ? x3 + 1.0f : expf(x3);
            }
            st[cc * TSTR + r]           = __float2half_rn(x0);
            st[(cc + 1) * TSTR + r]     = __float2half_rn(x1);
            st[cc * TSTR + r + 8]       = __float2half_rn(x2);
            st[(cc + 1) * TSTR + r + 8] = __float2half_rn(x3);
        }
    __syncthreads();

    const int b  = row0 >> 13;        // /8192
    const int n0 = row0 & 8191;
#pragma unroll
    for (int i = 0; i < 8; i++) {
        int flat = t + i * 256;
        int col = flat >> 4, seg = flat & 15;
        uint4 val = *(const uint4*)&st[col * TSTR + seg * 8];
        int g = col0 + col;
        __half* dst;
        if (g < 256) {        // k^T [bh][d][n]
            dst = g_kt + ((size_t)((b * PH + (g >> 5)) * DL + (g & 31))) * PN + n0 + seg * 8;
        } else {              // v^T [bh][c][n]
            int gv = g - 256;
            dst = g_vt + ((size_t)((b * PH + (gv >> 6)) * DC + (gv & 63))) * PN + n0 + seg * 8;
        }
        *(uint4*)dst = val;
    }
}

// ===================== kv aggregation via tensor cores =====================
// Per (b,h): kv[c,d] = sum_n v^T[c][n] * k^T[d][n]; ksum[d] = sum_n k^T[d][n].
// grid (32, 16 ksplits), 128 threads. M=64, N=32, K=512 per CTA, fp32 atomics.
#define KA_BK 64
#define KA_AW (64 * SWORD)    // 2560 words
#define KA_BW (32 * SWORD)    // 1280 words
#define KSPLIT 16
#define KA_NCH (PN / KSPLIT / KA_BK)   // 8

__global__ __launch_bounds__(128) void kv_accum_kernel()
{
    __shared__ uint32_t sbuf[2 * (KA_AW + KA_BW)];   // 30720 B

    const int bh = blockIdx.x;
    const int n0 = blockIdx.y * (PN / KSPLIT);
    const int t = threadIdx.x;
    const int w = t >> 5, lane = t & 31, lr = lane >> 2, lc = lane & 3;

    const __half* At = g_vt + (size_t)bh * DC * PN;
    const __half* Bt = g_kt + (size_t)bh * DL * PN;

    uint32_t* As = sbuf;
    uint32_t* Bs = sbuf + 2 * KA_AW;

    auto stage = [&](int c, int buf) {
        const __half* Ag = At + n0 + c * KA_BK;
        const __half* Bg = Bt + n0 + c * KA_BK;
        uint32_t* Ad = As + buf * KA_AW;
        uint32_t* Bd = Bs + buf * KA_BW;
#pragma unroll
        for (int i = 0; i < 4; i++) {
            int idx = i * 128 + t;
            int r = idx >> 3, seg = idx & 7;
            asm volatile("cp.async.cg.shared.global [%0], [%1], 16;"
                :: "r"(smem_u32(Ad + r * SWORD + seg * 4)),
                   "l"(Ag + (size_t)r * PN + seg * 8));
        }
#pragma unroll
        for (int i = 0; i < 2; i++) {
            int idx = i * 128 + t;
            int r = idx >> 3, seg = idx & 7;
            asm volatile("cp.async.cg.shared.global [%0], [%1], 16;"
                :: "r"(smem_u32(Bd + r * SWORD + seg * 4)),
                   "l"(Bg + (size_t)r * PN + seg * 8));
        }
        asm volatile("cp.async.commit_group;" ::: "memory");
    };

    float acc[4][4];
#pragma unroll
    for (int ni = 0; ni < 4; ni++)
#pragma unroll
        for (int j = 0; j < 4; j++) acc[ni][j] = 0.0f;
    float ksacc = 0.0f;

    auto compute = [&](int buf) {
        const uint32_t* Ab = As + buf * KA_AW;
        const uint32_t* Bb = Bs + buf * KA_BW;
#pragma unroll
        for (int j = 0; j < 4; j++) {
            const int ko = 8 * j + 2 * lc;
            uint32_t af[4];
            uint2 lo = *(const uint2*)&Ab[(16 * w + lr) * SWORD + ko];
            uint2 hi = *(const uint2*)&Ab[(16 * w + lr + 8) * SWORD + ko];
            af[0] = lo.x; af[1] = hi.x; af[2] = lo.y; af[3] = hi.y;
#pragma unroll
            for (int ni = 0; ni < 4; ni++) {
                uint2 b = *(const uint2*)&Bb[(ni * 8 + lr) * SWORD + ko];
                asm volatile(
                    "mma.sync.aligned.m16n8k16.row.col.f32.f16.f16.f32 "
                    "{%0,%1,%2,%3}, {%4,%5,%6,%7}, {%8,%9}, {%0,%1,%2,%3};"
                    : "+f"(acc[ni][0]), "+f"(acc[ni][1]),
                      "+f"(acc[ni][2]), "+f"(acc[ni][3])
                    : "r"(af[0]), "r"(af[1]), "r"(af[2]), "r"(af[3]),
                      "r"(b.x), "r"(b.y));
            }
        }
        const uint32_t* kp = Bb + (t >> 2) * SWORD + (t & 3) * 8;
#pragma unroll
        for (int i = 0; i < 8; i++) {
            float2 f = __half22float2(*(const __half2*)&kp[i]);
            ksacc += f.x + f.y;
        }
    };

    stage(0, 0);
    for (int c = 0; c < KA_NCH; c++) {
        if (c + 1 < KA_NCH) {
            stage(c + 1, (c + 1) & 1);
            asm volatile("cp.async.wait_group 1;" ::: "memory");
        } else {
            asm volatile("cp.async.wait_group 0;" ::: "memory");
        }
        __syncthreads();
        compute(c & 1);
        __syncthreads();
    }

    float* kv = g_acc;
#pragma unroll
    for (int ni = 0; ni < 4; ni++) {
        int d  = ni * 8 + 2 * lc;
        int c0 = 16 * w + lr;
        atomicAdd(&kv[((size_t)bh * DC + c0) * DL + d],         acc[ni][0]);
        atomicAdd(&kv[((size_t)bh * DC + c0) * DL + d + 1],     acc[ni][1]);
        atomicAdd(&kv[((size_t)bh * DC + c0 + 8) * DL + d],     acc[ni][2]);
        atomicAdd(&kv[((size_t)bh * DC + c0 + 8) * DL + d + 1], acc[ni][3]);
    }
    ksacc += __shfl_xor_sync(0xffffffffu, ksacc, 1);
    ksacc += __shfl_xor_sync(0xffffffffu, ksacc, 2);
    if ((t & 3) == 0)
        atomicAdd(&g_acc[PB * PH * DC * DL + bh * DL + (t >> 2)], ksacc);
}

// ===================== output kernel =====================
// grid (2, 64), 256 threads. bx -> head group (0 or 4), by -> 128 q rows.
// out[b,m,h,c] = z * sum_d q[m,h,d] * kv[b,h,c,d], z = 1/(q . ksum + eps)
__global__ __launch_bounds__(256) void out_kernel(float* __restrict__ out)
{
    __shared__ float kvs[4 * DC * DL];   // 4 heads x [64][32]
    __shared__ float kss[4 * DL];

    const int t = threadIdx.x;
    const int row0 = blockIdx.y * 128;   // global q row
    const int h0 = blockIdx.x * 4;       // head base
    const int b = row0 / PM;

    const float* kvg = g_acc + (size_t)(b * PH + h0) * DC * DL;
#pragma unroll
    for (int i = 0; i < 32; i++)
        kvs[t + i * 256] = kvg[t + i * 256];
    if (t < 128)
        kss[t] = g_acc[PB * PH * DC * DL + (b * PH + h0) * DL + t];
    __syncthreads();

    const int w = t >> 5, lane = t & 31;
    const int hl = w & 3;
    const int hg = h0 + hl;
    const int rb = (w >> 2) * 64;
    const float* kvh = kvs + hl * DC * DL;
    const float* ksh = kss + hl * DL;

#pragma unroll
    for (int p = 0; p < 2; p++) {
        int m = rb + p * 32 + lane;      // local row 0..127
        // load q: 32 fp16 for (row0+m, head hg)
        const uint4* qp16 = (const uint4*)&g_qp[(size_t)(row0 + m) * PL + hg * DL];
        float4 qv[8];
#pragma unroll
        for (int i = 0; i < 4; i++) {
            uint4 u = qp16[i];
            float2 f0 = __half22float2(*(__half2*)&u.x);
            float2 f1 = __half22float2(*(__half2*)&u.y);
            float2 f2 = __half22float2(*(__half2*)&u.z);
            float2 f3 = __half22float2(*(__half2*)&u.w);
            qv[2 * i]     = make_float4(f0.x, f0.y, f1.x, f1.y);
            qv[2 * i + 1] = make_float4(f2.x, f2.y, f3.x, f3.y);
        }

        float zp = 0.0f;
#pragma unroll
        for (int i = 0; i < 8; i++) {
            float4 k4 = ((const float4*)ksh)[i];
            zp += qv[i].x * k4.x + qv[i].y * k4.y + qv[i].z * k4.z + qv[i].w * k4.w;
        }
        float z = 1.0f / (zp + EPS);

        size_t obase = (size_t)(row0 + m) * PC + hg * DC;
        for (int c4 = 0; c4 < 16; c4++) {
            float o[4];
#pragma unroll
            for (int cc = 0; cc < 4; cc++) {
                const float4* kp = (const float4*)&kvh[(c4 * 4 + cc) * DL];
                float s = 0.0f;
#pragma unroll
                for (int i = 0; i < 8; i++) {
                    float4 k4 = kp[i];
                    s += qv[i].x * k4.x + qv[i].y * k4.y +
                         qv[i].z * k4.z + qv[i].w * k4.w;
                }
                o[cc] = z * s;
            }
            float4 st = {o[0], o[1], o[2], o[3]};
            *(float4*)&out[obase + c4 * 4] = st;
        }
    }
}

// ---------------------------------------------------------------------
extern "C" void kernel_launch(void* const* d_in, const int* in_sizes, int n_in,
                              void* d_out, int out_size)
{
    const float* input = (const float*)d_in[0];
    const float* query = (const float*)d_in[1];
    const float* Wq    = (const float*)d_in[2];
    const float* bq    = (const float*)d_in[3];
    const float* Wk    = (const float*)d_in[4];
    const float* bk    = (const float*)d_in[5];
    const float* Wv    = (const float*)d_in[6];
    const float* bv    = (const float*)d_in[7];
    float* out = (float*)d_out;
    (void)in_sizes; (void)n_in; (void)out_size;

    cudaFuncSetAttribute(kvq_gemm_kernel,
                         cudaFuncAttributeMaxDynamicSharedMemorySize, SMEM_GEMM);

    // 1) prep: weight transposes (fp16) + bias gather + zero acc
    prep_kernel<<<dim3(32, 16), dim3(32, 8)>>>(Wk, Wv, Wq, bk, bv, bq);

    // 2) convert X and Q to fp16
    const int ncv = (PB * PN * PC + PB * PM * PC) / 4;
    convert_kernel<<<(ncv + 255) / 256, 256>>>(input, query);

    // 3) combined k|v|q projection GEMM (fp16 tensor cores)
    kvq_gemm_kernel<<<dim3(8, 256), 256, SMEM_GEMM>>>();

    // 4) kv / ksum aggregation on tensor cores
    kv_accum_kernel<<<dim3(32, KSPLIT), 128>>>();

    // 5) output
    out_kernel<<<dim3(2, 64), 256>>>(out);
}

// round 9
// speedup vs baseline: 1.0122x; 1.0122x over previous
#include <cuda_runtime.h>
#include <cuda_fp16.h>
#include <cstdint>
#include <math.h>

// Problem constants (LinearAttention_22943715295778)
#define PB 4
#define PN 8192
#define PM 2048
#define PC 512
#define PL 256
#define PH 8
#define DL 32   // L/H
#define DC 64   // C/H
#define EPS 1e-6f

#define NACC (PB*PH*DC*DL + PB*PH*DL)             // 66560

// -------- device-global scratch (allocation-free requirement) --------
__device__ __half g_kt[PB * PH * DL * PN];        // 16 MB : k^T [bh][d][n], fp16, post-elu
__device__ __half g_vt[PB * PH * DC * PN];        // 32 MB : v^T [bh][c][n], fp16
__device__ __half g_qp[PB * PM * PL];             //  4 MB : q [row][256], fp16, post-elu
__device__ float  g_acc[NACC];                    // kv (65536) + ksum (1024)
__device__ __half g_wth[1024 * PC];               // rows: [WkT 256][WvT 512][WqT 256], fp16
__device__ float  g_bias[1024];                   // [bk | bv | bq]

// ===================== helpers =====================
__device__ __forceinline__ uint32_t smem_u32(const void* p) {
    uint32_t a;
    asm("{ .reg .u64 t; cvta.to.shared.u64 t, %1; cvt.u32.u64 %0, t; }"
        : "=r"(a) : "l"(p));
    return a;
}
// pack two fp32 -> one fp16x2 register (F2FP.PACK)
__device__ __forceinline__ uint32_t pack_h2(float lo, float hi) {
    uint32_t r;
    asm("cvt.rn.f16x2.f32 %0, %1, %2;" : "=r"(r) : "f"(hi), "f"(lo));
    return r;
}

// ===================== prep: weight transposes + bias + zero =====================
__global__ __launch_bounds__(256) void prep_kernel(
    const float* __restrict__ Wk, const float* __restrict__ Wv,
    const float* __restrict__ Wq,
    const float* __restrict__ bk, const float* __restrict__ bv,
    const float* __restrict__ bq)
{
    __shared__ float tile[32][33];
    const int n0 = blockIdx.x * 32, k0 = blockIdx.y * 32;
    const float *W, *bsrc; int N, ns;
    if (n0 < 256)      { W = Wk; bsrc = bk; N = PL; ns = n0; }
    else if (n0 < 768) { W = Wv; bsrc = bv; N = PC; ns = n0 - 256; }
    else               { W = Wq; bsrc = bq; N = PL; ns = n0 - 768; }
    const int tx = threadIdx.x, ty = threadIdx.y;
    for (int i = ty; i < 32; i += 8)
        tile[i][tx] = W[(size_t)(k0 + i) * N + ns + tx];
    __syncthreads();
    for (int i = ty; i < 32; i += 8)
        g_wth[(size_t)(n0 + i) * PC + k0 + tx] = __float2half_rn(tile[tx][i]);
    if (blockIdx.y == 0 && ty == 0)
        g_bias[n0 + tx] = bsrc[ns + tx];
    if (blockIdx.y == 1) {
        int t = ty * 32 + tx;
#pragma unroll
        for (int i = 0; i < 9; i++) {
            int j = blockIdx.x * 256 + t + i * 8192;
            if (j < NACC) g_acc[j] = 0.0f;
        }
    }
}

// ===================== fp16 mma mainloop, fp32 A operand =====================
// CTA tile 128x128, BK=64, 2-stage cp.async. 8 warps (4M x 2N), warp 32x64.
// A staged as fp32 (converted to fp16 at fragment load); B staged fp16.
#define TMm 128
#define TNn 128
#define BKh 64
#define ASW 68                        // fp32 words per A row (64 + 4 pad)
#define BSW 40                        // uint32 words per B row (64 fp16 + pad)
#define ATILEW (128 * ASW)            // 8704 words
#define BTILEW (128 * BSW)            // 5120 words
#define NCHh (PC / BKh)               // 8
#define SMEM_GEMM ((2 * ATILEW + 2 * BTILEW) * 4)   // 110592 bytes

__device__ __forceinline__ void mma_tile_loop_f32a(
    const float* __restrict__ Ag0,    // fp32 A base (row stride 512 floats)
    const __half* __restrict__ Bg0,   // fp16 W^T base (row stride 512 halves)
    uint32_t* sm, int t, float acc[2][8][4])
{
    uint32_t* As = sm;                // fp32 tiles [2][128][ASW]
    uint32_t* Bs = sm + 2 * ATILEW;   // fp16 tiles [2][128][BSW]
    const int wid = t >> 5, lane = t & 31;
    const int lr = lane >> 2, lc = lane & 3;
    const int wm = (wid & 3) * 32, wn = (wid >> 2) * 64;

    auto stage = [&](int c, int buf) {
        const float*  Ag = Ag0 + c * BKh;
        const __half* Bg = Bg0 + c * BKh;
        uint32_t* Ad = As + buf * ATILEW;
        uint32_t* Bd = Bs + buf * BTILEW;
#pragma unroll
        for (int i = 0; i < 8; i++) {           // A: 128 rows x 16 segs (16B)
            int idx = i * 256 + t;
            int r = idx >> 4, s = idx & 15;
            asm volatile("cp.async.cg.shared.global [%0], [%1], 16;"
                :: "r"(smem_u32(Ad + r * ASW + s * 4)),
                   "l"(Ag + (size_t)r * PC + s * 4));
        }
#pragma unroll
        for (int i = 0; i < 4; i++) {           // B: 128 rows x 8 segs (16B)
            int idx = i * 256 + t;
            int r = idx >> 3, s = idx & 7;
            asm volatile("cp.async.cg.shared.global [%0], [%1], 16;"
                :: "r"(smem_u32(Bd + r * BSW + s * 4)),
                   "l"(Bg + (size_t)r * PC + s * 8));
        }
        asm volatile("cp.async.commit_group;" ::: "memory");
    };

    auto compute = [&](int buf) {
        const uint32_t* Ab = As + buf * ATILEW;
        const uint32_t* Bb = Bs + buf * BTILEW;
#pragma unroll
        for (int j = 0; j < 4; j++) {
            uint32_t af[2][4], bf[8][2];
#pragma unroll
            for (int mi = 0; mi < 2; mi++) {
                const int r0 = wm + mi * 16 + lr;
                float4 f0 = *(const float4*)(Ab + r0 * ASW + 16 * j + 4 * lc);
                float4 f1 = *(const float4*)(Ab + (r0 + 8) * ASW + 16 * j + 4 * lc);
                af[mi][0] = pack_h2(f0.x, f0.y);
                af[mi][2] = pack_h2(f0.z, f0.w);
                af[mi][1] = pack_h2(f1.x, f1.y);
                af[mi][3] = pack_h2(f1.z, f1.w);
            }
            const int ko = 8 * j + 2 * lc;
#pragma unroll
            for (int ni = 0; ni < 8; ni++) {
                uint2 b = *(const uint2*)&Bb[(wn + ni * 8 + lr) * BSW + ko];
                bf[ni][0] = b.x; bf[ni][1] = b.y;
            }
#pragma unroll
            for (int mi = 0; mi < 2; mi++)
#pragma unroll
                for (int ni = 0; ni < 8; ni++)
                    asm volatile(
                        "mma.sync.aligned.m16n8k16.row.col.f32.f16.f16.f32 "
                        "{%0,%1,%2,%3}, {%4,%5,%6,%7}, {%8,%9}, {%0,%1,%2,%3};"
                        : "+f"(acc[mi][ni][0]), "+f"(acc[mi][ni][1]),
                          "+f"(acc[mi][ni][2]), "+f"(acc[mi][ni][3])
                        : "r"(af[mi][0]), "r"(af[mi][1]),
                          "r"(af[mi][2]), "r"(af[mi][3]),
                          "r"(bf[ni][0]), "r"(bf[ni][1]));
        }
    };

    stage(0, 0);
    for (int c = 0; c < NCHh; c++) {
        if (c + 1 < NCHh) {
            stage(c + 1, (c + 1) & 1);
            asm volatile("cp.async.wait_group 1;" ::: "memory");
        } else {
            asm volatile("cp.async.wait_group 0;" ::: "memory");
        }
        __syncthreads();
        compute(c & 1);
        __syncthreads();
    }
}

// ===================== combined k|v|q projection GEMM =====================
// 1-D grid of 1536 + 128 CTAs. id<1536: kv projection of X (transposed fp16
// out). id>=1536: q projection of Q (row-major fp16 out).
#define TSTR 136   // fp16 stride of transpose buffer rows

__global__ __launch_bounds__(256, 2) void kvq_gemm_kernel(
    const float* __restrict__ X, const float* __restrict__ Q)
{
    const int id = blockIdx.x;
    const bool isq = (id >= 1536);
    int row0, col0;
    const float* Ag0;
    if (isq) {
        int j = id - 1536;
        col0 = 768 + (j & 1) * TNn;
        row0 = (j >> 1) * TMm;
        Ag0 = Q + (size_t)row0 * PC;
    } else {
        col0 = (id % 6) * TNn;
        row0 = (id / 6) * TMm;
        Ag0 = X + (size_t)row0 * PC;
    }

    extern __shared__ uint32_t smw[];
    const int t = threadIdx.x;

    float acc[2][8][4];
#pragma unroll
    for (int mi = 0; mi < 2; mi++)
#pragma unroll
        for (int ni = 0; ni < 8; ni++)
#pragma unroll
            for (int j = 0; j < 4; j++) acc[mi][ni][j] = 0.0f;

    mma_tile_loop_f32a(Ag0, g_wth + (size_t)col0 * PC, smw, t, acc);
    // ends with __syncthreads(); smem reusable.

    const int wid = t >> 5, lane = t & 31, lr = lane >> 2, lc = lane & 3;
    const int wm = (wid & 3) * 32, wn = (wid >> 2) * 64;

    if (isq) {
        // q: direct fp16 row-major stores to g_qp [8192][256]
#pragma unroll
        for (int mi = 0; mi < 2; mi++)
#pragma unroll
            for (int ni = 0; ni < 8; ni++) {
                int r  = row0 + wm + mi * 16 + lr;
                int cb = wn + ni * 8 + 2 * lc;
                int cc = (col0 - 768) + cb;
                float b0 = g_bias[col0 + cb];
                float b1 = g_bias[col0 + cb + 1];
                float x0 = acc[mi][ni][0] + b0;
                float x1 = acc[mi][ni][1] + b1;
                float x2 = acc[mi][ni][2] + b0;
                float x3 = acc[mi][ni][3] + b1;
                x0 = x0 > 0.0f ? x0 + 1.0f : expf(x0);
                x1 = x1 > 0.0f ? x1 + 1.0f : expf(x1);
                x2 = x2 > 0.0f ? x2 + 1.0f : expf(x2);
                x3 = x3 > 0.0f ? x3 + 1.0f : expf(x3);
                *(uint32_t*)&g_qp[(size_t)r * PL + cc]       = pack_h2(x0, x1);
                *(uint32_t*)&g_qp[(size_t)(r + 8) * PL + cc] = pack_h2(x2, x3);
            }
        return;
    }

    const bool elu = (col0 < 256);
    __half* st = (__half*)smw;   // [128 cols][TSTR]
#pragma unroll
    for (int mi = 0; mi < 2; mi++)
#pragma unroll
        for (int ni = 0; ni < 8; ni++) {
            int r  = wm + mi * 16 + lr;
            int cc = wn + ni * 8 + 2 * lc;
            float b0 = g_bias[col0 + cc], b1 = g_bias[col0 + cc + 1];
            float x0 = acc[mi][ni][0] + b0;
            float x1 = acc[mi][ni][1] + b1;
            float x2 = acc[mi][ni][2] + b0;
            float x3 = acc[mi][ni][3] + b1;
            if (elu) {
                x0 = x0 > 0.0f ? x0 + 1.0f : expf(x0);
                x1 = x1 > 0.0f ? x1 + 1.0f : expf(x1);
                x2 = x2 > 0.0f ? x2 + 1.0f : expf(x2);
                x3 = x3 > 0.0f ? x3 + 1.0f : expf(x3);
            }
            st[cc * TSTR + r]           = __float2half_rn(x0);
            st[(cc + 1) * TSTR + r]     = __float2half_rn(x1);
            st[cc * TSTR + r + 8]       = __float2half_rn(x2);
            st[(cc + 1) * TSTR + r + 8] = __float2half_rn(x3);
        }
    __syncthreads();

    const int b  = row0 >> 13;        // /8192
    const int n0 = row0 & 8191;
#pragma unroll
    for (int i = 0; i < 8; i++) {
        int flat = t + i * 256;
        int col = flat >> 4, seg = flat & 15;
        uint4 val = *(const uint4*)&st[col * TSTR + seg * 8];
        int g = col0 + col;
        __half* dst;
        if (g < 256) {        // k^T [bh][d][n]
            dst = g_kt + ((size_t)((b * PH + (g >> 5)) * DL + (g & 31))) * PN + n0 + seg * 8;
        } else {              // v^T [bh][c][n]
            int gv = g - 256;
            dst = g_vt + ((size_t)((b * PH + (gv >> 6)) * DC + (gv & 63))) * PN + n0 + seg * 8;
        }
        *(uint4*)dst = val;
    }
}

// ===================== kv aggregation via tensor cores =====================
// Per (b,h): kv[c,d] = sum_n v^T[c][n] * k^T[d][n]; ksum[d] = sum_n k^T[d][n].
#define KA_BK 64
#define KA_AW (64 * BSW)      // 2560 words
#define KA_BW (32 * BSW)      // 1280 words
#define KSPLIT 16
#define KA_NCH (PN / KSPLIT / KA_BK)   // 8

__global__ __launch_bounds__(128) void kv_accum_kernel()
{
    __shared__ uint32_t sbuf[2 * (KA_AW + KA_BW)];   // 30720 B

    const int bh = blockIdx.x;
    const int n0 = blockIdx.y * (PN / KSPLIT);
    const int t = threadIdx.x;
    const int w = t >> 5, lane = t & 31, lr = lane >> 2, lc = lane & 3;

    const __half* At = g_vt + (size_t)bh * DC * PN;
    const __half* Bt = g_kt + (size_t)bh * DL * PN;

    uint32_t* As = sbuf;
    uint32_t* Bs = sbuf + 2 * KA_AW;

    auto stage = [&](int c, int buf) {
        const __half* Ag = At + n0 + c * KA_BK;
        const __half* Bg = Bt + n0 + c * KA_BK;
        uint32_t* Ad = As + buf * KA_AW;
        uint32_t* Bd = Bs + buf * KA_BW;
#pragma unroll
        for (int i = 0; i < 4; i++) {
            int idx = i * 128 + t;
            int r = idx >> 3, seg = idx & 7;
            asm volatile("cp.async.cg.shared.global [%0], [%1], 16;"
                :: "r"(smem_u32(Ad + r * BSW + seg * 4)),
                   "l"(Ag + (size_t)r * PN + seg * 8));
        }
#pragma unroll
        for (int i = 0; i < 2; i++) {
            int idx = i * 128 + t;
            int r = idx >> 3, seg = idx & 7;
            asm volatile("cp.async.cg.shared.global [%0], [%1], 16;"
                :: "r"(smem_u32(Bd + r * BSW + seg * 4)),
                   "l"(Bg + (size_t)r * PN + seg * 8));
        }
        asm volatile("cp.async.commit_group;" ::: "memory");
    };

    float acc[4][4];
#pragma unroll
    for (int ni = 0; ni < 4; ni++)
#pragma unroll
        for (int j = 0; j < 4; j++) acc[ni][j] = 0.0f;
    float ksacc = 0.0f;

    auto compute = [&](int buf) {
        const uint32_t* Ab = As + buf * KA_AW;
        const uint32_t* Bb = Bs + buf * KA_BW;
#pragma unroll
        for (int j = 0; j < 4; j++) {
            const int ko = 8 * j + 2 * lc;
            uint32_t af[4];
            uint2 lo = *(const uint2*)&Ab[(16 * w + lr) * BSW + ko];
            uint2 hi = *(const uint2*)&Ab[(16 * w + lr + 8) * BSW + ko];
            af[0] = lo.x; af[1] = hi.x; af[2] = lo.y; af[3] = hi.y;
#pragma unroll
            for (int ni = 0; ni < 4; ni++) {
                uint2 b = *(const uint2*)&Bb[(ni * 8 + lr) * BSW + ko];
                asm volatile(
                    "mma.sync.aligned.m16n8k16.row.col.f32.f16.f16.f32 "
                    "{%0,%1,%2,%3}, {%4,%5,%6,%7}, {%8,%9}, {%0,%1,%2,%3};"
                    : "+f"(acc[ni][0]), "+f"(acc[ni][1]),
                      "+f"(acc[ni][2]), "+f"(acc[ni][3])
                    : "r"(af[0]), "r"(af[1]), "r"(af[2]), "r"(af[3]),
                      "r"(b.x), "r"(b.y));
            }
        }
        const uint32_t* kp = Bb + (t >> 2) * BSW + (t & 3) * 8;
#pragma unroll
        for (int i = 0; i < 8; i++) {
            float2 f = __half22float2(*(const __half2*)&kp[i]);
            ksacc += f.x + f.y;
        }
    };

    stage(0, 0);
    for (int c = 0; c < KA_NCH; c++) {
        if (c + 1 < KA_NCH) {
            stage(c + 1, (c + 1) & 1);
            asm volatile("cp.async.wait_group 1;" ::: "memory");
        } else {
            asm volatile("cp.async.wait_group 0;" ::: "memory");
        }
        __syncthreads();
        compute(c & 1);
        __syncthreads();
    }

    float* kv = g_acc;
#pragma unroll
    for (int ni = 0; ni < 4; ni++) {
        int d  = ni * 8 + 2 * lc;
        int c0 = 16 * w + lr;
        atomicAdd(&kv[((size_t)bh * DC + c0) * DL + d],         acc[ni][0]);
        atomicAdd(&kv[((size_t)bh * DC + c0) * DL + d + 1],     acc[ni][1]);
        atomicAdd(&kv[((size_t)bh * DC + c0 + 8) * DL + d],     acc[ni][2]);
        atomicAdd(&kv[((size_t)bh * DC + c0 + 8) * DL + d + 1], acc[ni][3]);
    }
    ksacc += __shfl_xor_sync(0xffffffffu, ksacc, 1);
    ksacc += __shfl_xor_sync(0xffffffffu, ksacc, 2);
    if ((t & 3) == 0)
        atomicAdd(&g_acc[PB * PH * DC * DL + bh * DL + (t >> 2)], ksacc);
}

// ===================== output kernel =====================
// grid (2, 64), 256 threads. bx -> head group (0 or 4), by -> 128 q rows.
__global__ __launch_bounds__(256) void out_kernel(float* __restrict__ out)
{
    __shared__ float kvs[4 * DC * DL];   // 4 heads x [64][32]
    __shared__ float kss[4 * DL];

    const int t = threadIdx.x;
    const int row0 = blockIdx.y * 128;
    const int h0 = blockIdx.x * 4;
    const int b = row0 / PM;

    const float* kvg = g_acc + (size_t)(b * PH + h0) * DC * DL;
#pragma unroll
    for (int i = 0; i < 32; i++)
        kvs[t + i * 256] = kvg[t + i * 256];
    if (t < 128)
        kss[t] = g_acc[PB * PH * DC * DL + (b * PH + h0) * DL + t];
    __syncthreads();

    const int w = t >> 5, lane = t & 31;
    const int hl = w & 3;
    const int hg = h0 + hl;
    const int rb = (w >> 2) * 64;
    const float* kvh = kvs + hl * DC * DL;
    const float* ksh = kss + hl * DL;

#pragma unroll
    for (int p = 0; p < 2; p++) {
        int m = rb + p * 32 + lane;
        const uint4* qp16 = (const uint4*)&g_qp[(size_t)(row0 + m) * PL + hg * DL];
        float4 qv[8];
#pragma unroll
        for (int i = 0; i < 4; i++) {
            uint4 u = qp16[i];
            float2 f0 = __half22float2(*(__half2*)&u.x);
            float2 f1 = __half22float2(*(__half2*)&u.y);
            float2 f2 = __half22float2(*(__half2*)&u.z);
            float2 f3 = __half22float2(*(__half2*)&u.w);
            qv[2 * i]     = make_float4(f0.x, f0.y, f1.x, f1.y);
            qv[2 * i + 1] = make_float4(f2.x, f2.y, f3.x, f3.y);
        }

        float zp = 0.0f;
#pragma unroll
        for (int i = 0; i < 8; i++) {
            float4 k4 = ((const float4*)ksh)[i];
            zp += qv[i].x * k4.x + qv[i].y * k4.y + qv[i].z * k4.z + qv[i].w * k4.w;
        }
        float z = 1.0f / (zp + EPS);

        size_t obase = (size_t)(row0 + m) * PC + hg * DC;
        for (int c4 = 0; c4 < 16; c4++) {
            float o[4];
#pragma unroll
            for (int cc = 0; cc < 4; cc++) {
                const float4* kp = (const float4*)&kvh[(c4 * 4 + cc) * DL];
                float s = 0.0f;
#pragma unroll
                for (int i = 0; i < 8; i++) {
                    float4 k4 = kp[i];
                    s += qv[i].x * k4.x + qv[i].y * k4.y +
                         qv[i].z * k4.z + qv[i].w * k4.w;
                }
                o[cc] = z * s;
            }
            float4 st = {o[0], o[1], o[2], o[3]};
            *(float4*)&out[obase + c4 * 4] = st;
        }
    }
}

// ---------------------------------------------------------------------
extern "C" void kernel_launch(void* const* d_in, const int* in_sizes, int n_in,
                              void* d_out, int out_size)
{
    const float* input = (const float*)d_in[0];
    const float* query = (const float*)d_in[1];
    const float* Wq    = (const float*)d_in[2];
    const float* bq    = (const float*)d_in[3];
    const float* Wk    = (const float*)d_in[4];
    const float* bk    = (const float*)d_in[5];
    const float* Wv    = (const float*)d_in[6];
    const float* bv    = (const float*)d_in[7];
    float* out = (float*)d_out;
    (void)in_sizes; (void)n_in; (void)out_size;

    cudaFuncSetAttribute(kvq_gemm_kernel,
                         cudaFuncAttributeMaxDynamicSharedMemorySize, SMEM_GEMM);

    // 1) prep: weight transposes (fp16) + bias gather + zero acc
    prep_kernel<<<dim3(32, 16), dim3(32, 8)>>>(Wk, Wv, Wq, bk, bv, bq);

    // 2) combined k|v|q projection GEMM (fp32 A staged, fp16 tensor cores)
    kvq_gemm_kernel<<<1536 + 128, 256, SMEM_GEMM>>>(input, query);

    // 3) kv / ksum aggregation on tensor cores
    kv_accum_kernel<<<dim3(32, KSPLIT), 128>>>();

    // 4) output
    out_kernel<<<dim3(2, 64), 256>>>(out);
}

// round 10
// speedup vs baseline: 1.3134x; 1.2976x over previous
#include <cuda_runtime.h>
#include <cuda_fp16.h>
#include <cstdint>
#include <math.h>

// Problem constants (LinearAttention_22943715295778)
#define PB 4
#define PN 8192
#define PM 2048
#define PC 512
#define PL 256
#define PH 8
#define DL 32   // L/H
#define DC 64   // C/H
#define EPS 1e-6f

#define NACC (PB*PH*DC*DL + PB*PH*DL)             // 66560

// -------- device-global scratch (allocation-free requirement) --------
__device__ __half g_kt[PB * PH * DL * PN];        // 16 MB : k^T [bh][d][n], fp16, post-elu
__device__ __half g_vt[PB * PH * DC * PN];        // 32 MB : v^T [bh][c][n], fp16
__device__ __half g_qp[PB * PM * PL];             //  4 MB : q [row][256], fp16, post-elu
__device__ float  g_acc[NACC];                    // kv (65536) + ksum (1024)
__device__ __half g_wth[1024 * PC];               // rows: [WkT 256][WvT 512][WqT 256], fp16
__device__ float  g_bias[1024];                   // [bk | bv | bq]

// ===================== helpers =====================
__device__ __forceinline__ uint32_t smem_u32(const void* p) {
    uint32_t a;
    asm("{ .reg .u64 t; cvta.to.shared.u64 t, %1; cvt.u32.u64 %0, t; }"
        : "=r"(a) : "l"(p));
    return a;
}
// pack two fp32 -> one fp16x2 register (F2FP.PACK)
__device__ __forceinline__ uint32_t pack_h2(float lo, float hi) {
    uint32_t r;
    asm("cvt.rn.f16x2.f32 %0, %1, %2;" : "=r"(r) : "f"(hi), "f"(lo));
    return r;
}

// ===================== prep: weight transposes + bias + zero =====================
__global__ __launch_bounds__(256) void prep_kernel(
    const float* __restrict__ Wk, const float* __restrict__ Wv,
    const float* __restrict__ Wq,
    const float* __restrict__ bk, const float* __restrict__ bv,
    const float* __restrict__ bq)
{
    __shared__ float tile[32][33];
    const int n0 = blockIdx.x * 32, k0 = blockIdx.y * 32;
    const float *W, *bsrc; int N, ns;
    if (n0 < 256)      { W = Wk; bsrc = bk; N = PL; ns = n0; }
    else if (n0 < 768) { W = Wv; bsrc = bv; N = PC; ns = n0 - 256; }
    else               { W = Wq; bsrc = bq; N = PL; ns = n0 - 768; }
    const int tx = threadIdx.x, ty = threadIdx.y;
    for (int i = ty; i < 32; i += 8)
        tile[i][tx] = W[(size_t)(k0 + i) * N + ns + tx];
    __syncthreads();
    for (int i = ty; i < 32; i += 8)
        g_wth[(size_t)(n0 + i) * PC + k0 + tx] = __float2half_rn(tile[tx][i]);
    if (blockIdx.y == 0 && ty == 0)
        g_bias[n0 + tx] = bsrc[ns + tx];
    if (blockIdx.y == 1) {
        int t = ty * 32 + tx;
#pragma unroll
        for (int i = 0; i < 9; i++) {
            int j = blockIdx.x * 256 + t + i * 8192;
            if (j < NACC) g_acc[j] = 0.0f;
        }
    }
}

// ===================== fp16 mma mainloop, fp32 A operand =====================
// CTA tile 128x128, BK=64, 2-stage cp.async. 8 warps (4M x 2N), warp 32x64.
// A staged fp32 with XOR seg-swizzle (conflict-free LDS.128, no padding);
// converted to fp16 at fragment load. B staged fp16.
#define TMm 128
#define TNn 128
#define BKh 64
#define ASW 64                        // fp32 words per A row (no pad; swizzled)
#define BSW 40                        // uint32 words per B row (64 fp16 + pad)
#define ATILEW (128 * ASW)            // 8192 words
#define BTILEW (128 * BSW)            // 5120 words
#define NCHh (PC / BKh)               // 8
#define SMEM_GEMM ((2 * ATILEW + 2 * BTILEW) * 4)   // 106496 bytes

__device__ __forceinline__ void mma_tile_loop_f32a(
    const float* __restrict__ Ag0,    // fp32 A base (row stride 512 floats)
    const __half* __restrict__ Bg0,   // fp16 W^T base (row stride 512 halves)
    uint32_t* sm, int t, float acc[2][8][4])
{
    uint32_t* As = sm;                // fp32 tiles [2][128][ASW]
    uint32_t* Bs = sm + 2 * ATILEW;   // fp16 tiles [2][128][BSW]
    const int wid = t >> 5, lane = t & 31;
    const int lr = lane >> 2, lc = lane & 3;
    const int wm = (wid & 3) * 32, wn = (wid >> 2) * 64;

    auto stage = [&](int c, int buf) {
        const float*  Ag = Ag0 + c * BKh;
        const __half* Bg = Bg0 + c * BKh;
        uint32_t* Ad = As + buf * ATILEW;
        uint32_t* Bd = Bs + buf * BTILEW;
#pragma unroll
        for (int i = 0; i < 8; i++) {           // A: 128 rows x 16 segs (16B)
            int idx = i * 256 + t;
            int r = idx >> 4, s = idx & 15;
            int ss = s ^ ((r & 1) << 2);        // XOR swizzle
            asm volatile("cp.async.cg.shared.global [%0], [%1], 16;"
                :: "r"(smem_u32(Ad + r * ASW + ss * 4)),
                   "l"(Ag + (size_t)r * PC + s * 4));
        }
#pragma unroll
        for (int i = 0; i < 4; i++) {           // B: 128 rows x 8 segs (16B)
            int idx = i * 256 + t;
            int r = idx >> 3, s = idx & 7;
            asm volatile("cp.async.cg.shared.global [%0], [%1], 16;"
                :: "r"(smem_u32(Bd + r * BSW + s * 4)),
                   "l"(Bg + (size_t)r * PC + s * 8));
        }
        asm volatile("cp.async.commit_group;" ::: "memory");
    };

    auto compute = [&](int buf) {
        const uint32_t* Ab = As + buf * ATILEW;
        const uint32_t* Bb = Bs + buf * BTILEW;
        const int asw = (lr & 1) << 2;          // seg XOR = j^1 for odd rows
#pragma unroll
        for (int j = 0; j < 4; j++) {
            uint32_t af[2][4], bf[8][2];
            const int aoff = 16 * (j ^ (asw >> 2)) + 4 * lc;
#pragma unroll
            for (int mi = 0; mi < 2; mi++) {
                const int r0 = wm + mi * 16 + lr;
                float4 f0 = *(const float4*)(Ab + r0 * ASW + aoff);
                float4 f1 = *(const float4*)(Ab + (r0 + 8) * ASW + aoff);
                af[mi][0] = pack_h2(f0.x, f0.y);
                af[mi][2] = pack_h2(f0.z, f0.w);
                af[mi][1] = pack_h2(f1.x, f1.y);
                af[mi][3] = pack_h2(f1.z, f1.w);
            }
            const int ko = 8 * j + 2 * lc;
#pragma unroll
            for (int ni = 0; ni < 8; ni++) {
                uint2 b = *(const uint2*)&Bb[(wn + ni * 8 + lr) * BSW + ko];
                bf[ni][0] = b.x; bf[ni][1] = b.y;
            }
#pragma unroll
            for (int mi = 0; mi < 2; mi++)
#pragma unroll
                for (int ni = 0; ni < 8; ni++)
                    asm volatile(
                        "mma.sync.aligned.m16n8k16.row.col.f32.f16.f16.f32 "
                        "{%0,%1,%2,%3}, {%4,%5,%6,%7}, {%8,%9}, {%0,%1,%2,%3};"
                        : "+f"(acc[mi][ni][0]), "+f"(acc[mi][ni][1]),
                          "+f"(acc[mi][ni][2]), "+f"(acc[mi][ni][3])
                        : "r"(af[mi][0]), "r"(af[mi][1]),
                          "r"(af[mi][2]), "r"(af[mi][3]),
                          "r"(bf[ni][0]), "r"(bf[ni][1]));
        }
    };

    stage(0, 0);
    for (int c = 0; c < NCHh; c++) {
        if (c + 1 < NCHh) {
            stage(c + 1, (c + 1) & 1);
            asm volatile("cp.async.wait_group 1;" ::: "memory");
        } else {
            asm volatile("cp.async.wait_group 0;" ::: "memory");
        }
        __syncthreads();
        compute(c & 1);
        __syncthreads();
    }
}

// ===================== combined k|v|q projection GEMM =====================
// 1-D grid of 1536 + 128 CTAs. id<1536: kv projection of X (transposed fp16
// out). id>=1536: q projection of Q (row-major fp16 out).
#define TSTR 136   // fp16 stride of transpose buffer rows

__global__ __launch_bounds__(256, 2) void kvq_gemm_kernel(
    const float* __restrict__ X, const float* __restrict__ Q)
{
    const int id = blockIdx.x;
    const bool isq = (id >= 1536);
    int row0, col0;
    const float* Ag0;
    if (isq) {
        int j = id - 1536;
        col0 = 768 + (j & 1) * TNn;
        row0 = (j >> 1) * TMm;
        Ag0 = Q + (size_t)row0 * PC;
    } else {
        col0 = (id % 6) * TNn;
        row0 = (id / 6) * TMm;
        Ag0 = X + (size_t)row0 * PC;
    }

    extern __shared__ uint32_t smw[];
    const int t = threadIdx.x;

    float acc[2][8][4];
#pragma unroll
    for (int mi = 0; mi < 2; mi++)
#pragma unroll
        for (int ni = 0; ni < 8; ni++)
#pragma unroll
            for (int j = 0; j < 4; j++) acc[mi][ni][j] = 0.0f;

    mma_tile_loop_f32a(Ag0, g_wth + (size_t)col0 * PC, smw, t, acc);
    // ends with __syncthreads(); smem reusable.

    const int wid = t >> 5, lane = t & 31, lr = lane >> 2, lc = lane & 3;
    const int wm = (wid & 3) * 32, wn = (wid >> 2) * 64;

    if (isq) {
        // q: direct fp16 row-major stores to g_qp [8192][256]
#pragma unroll
        for (int mi = 0; mi < 2; mi++)
#pragma unroll
            for (int ni = 0; ni < 8; ni++) {
                int r  = row0 + wm + mi * 16 + lr;
                int cb = wn + ni * 8 + 2 * lc;
                int cc = (col0 - 768) + cb;
                float b0 = g_bias[col0 + cb];
                float b1 = g_bias[col0 + cb + 1];
                float x0 = acc[mi][ni][0] + b0;
                float x1 = acc[mi][ni][1] + b1;
                float x2 = acc[mi][ni][2] + b0;
                float x3 = acc[mi][ni][3] + b1;
                x0 = x0 > 0.0f ? x0 + 1.0f : expf(x0);
                x1 = x1 > 0.0f ? x1 + 1.0f : expf(x1);
                x2 = x2 > 0.0f ? x2 + 1.0f : expf(x2);
                x3 = x3 > 0.0f ? x3 + 1.0f : expf(x3);
                *(uint32_t*)&g_qp[(size_t)r * PL + cc]       = pack_h2(x0, x1);
                *(uint32_t*)&g_qp[(size_t)(r + 8) * PL + cc] = pack_h2(x2, x3);
            }
        return;
    }

    const bool elu = (col0 < 256);
    __half* st = (__half*)smw;   // [128 cols][TSTR]
#pragma unroll
    for (int mi = 0; mi < 2; mi++)
#pragma unroll
        for (int ni = 0; ni < 8; ni++) {
            int r  = wm + mi * 16 + lr;
            int cc = wn + ni * 8 + 2 * lc;
            float b0 = g_bias[col0 + cc], b1 = g_bias[col0 + cc + 1];
            float x0 = acc[mi][ni][0] + b0;
            float x1 = acc[mi][ni][1] + b1;
            float x2 = acc[mi][ni][2] + b0;
            float x3 = acc[mi][ni][3] + b1;
            if (elu) {
                x0 = x0 > 0.0f ? x0 + 1.0f : expf(x0);
                x1 = x1 > 0.0f ? x1 + 1.0f : expf(x1);
                x2 = x2 > 0.0f ? x2 + 1.0f : expf(x2);
                x3 = x3 > 0.0f ? x3 + 1.0f : expf(x3);
            }
            st[cc * TSTR + r]           = __float2half_rn(x0);
            st[(cc + 1) * TSTR + r]     = __float2half_rn(x1);
            st[cc * TSTR + r + 8]       = __float2half_rn(x2);
            st[(cc + 1) * TSTR + r + 8] = __float2half_rn(x3);
        }
    __syncthreads();

    const int b  = row0 >> 13;        // /8192
    const int n0 = row0 & 8191;
#pragma unroll
    for (int i = 0; i < 8; i++) {
        int flat = t + i * 256;
        int col = flat >> 4, seg = flat & 15;
        uint4 val = *(const uint4*)&st[col * TSTR + seg * 8];
        int g = col0 + col;
        __half* dst;
        if (g < 256) {        // k^T [bh][d][n]
            dst = g_kt + ((size_t)((b * PH + (g >> 5)) * DL + (g & 31))) * PN + n0 + seg * 8;
        } else {              // v^T [bh][c][n]
            int gv = g - 256;
            dst = g_vt + ((size_t)((b * PH + (gv >> 6)) * DC + (gv & 63))) * PN + n0 + seg * 8;
        }
        *(uint4*)dst = val;
    }
}

// ===================== kv aggregation via tensor cores =====================
// Per (b,h): kv[c,d] = sum_n v^T[c][n] * k^T[d][n]; ksum[d] = sum_n k^T[d][n].
#define KA_BK 64
#define KA_AW (64 * BSW)      // 2560 words
#define KA_BW (32 * BSW)      // 1280 words
#define KSPLIT 16
#define KA_NCH (PN / KSPLIT / KA_BK)   // 8

__global__ __launch_bounds__(128) void kv_accum_kernel()
{
    __shared__ uint32_t sbuf[2 * (KA_AW + KA_BW)];   // 30720 B

    const int bh = blockIdx.x;
    const int n0 = blockIdx.y * (PN / KSPLIT);
    const int t = threadIdx.x;
    const int w = t >> 5, lane = t & 31, lr = lane >> 2, lc = lane & 3;

    const __half* At = g_vt + (size_t)bh * DC * PN;
    const __half* Bt = g_kt + (size_t)bh * DL * PN;

    uint32_t* As = sbuf;
    uint32_t* Bs = sbuf + 2 * KA_AW;

    auto stage = [&](int c, int buf) {
        const __half* Ag = At + n0 + c * KA_BK;
        const __half* Bg = Bt + n0 + c * KA_BK;
        uint32_t* Ad = As + buf * KA_AW;
        uint32_t* Bd = Bs + buf * KA_BW;
#pragma unroll
        for (int i = 0; i < 4; i++) {
            int idx = i * 128 + t;
            int r = idx >> 3, seg = idx & 7;
            asm volatile("cp.async.cg.shared.global [%0], [%1], 16;"
                :: "r"(smem_u32(Ad + r * BSW + seg * 4)),
                   "l"(Ag + (size_t)r * PN + seg * 8));
        }
#pragma unroll
        for (int i = 0; i < 2; i++) {
            int idx = i * 128 + t;
            int r = idx >> 3, seg = idx & 7;
            asm volatile("cp.async.cg.shared.global [%0], [%1], 16;"
                :: "r"(smem_u32(Bd + r * BSW + seg * 4)),
                   "l"(Bg + (size_t)r * PN + seg * 8));
        }
        asm volatile("cp.async.commit_group;" ::: "memory");
    };

    float acc[4][4];
#pragma unroll
    for (int ni = 0; ni < 4; ni++)
#pragma unroll
        for (int j = 0; j < 4; j++) acc[ni][j] = 0.0f;
    float ksacc = 0.0f;

    auto compute = [&](int buf) {
        const uint32_t* Ab = As + buf * KA_AW;
        const uint32_t* Bb = Bs + buf * KA_BW;
#pragma unroll
        for (int j = 0; j < 4; j++) {
            const int ko = 8 * j + 2 * lc;
            uint32_t af[4];
            uint2 lo = *(const uint2*)&Ab[(16 * w + lr) * BSW + ko];
            uint2 hi = *(const uint2*)&Ab[(16 * w + lr + 8) * BSW + ko];
            af[0] = lo.x; af[1] = hi.x; af[2] = lo.y; af[3] = hi.y;
#pragma unroll
            for (int ni = 0; ni < 4; ni++) {
                uint2 b = *(const uint2*)&Bb[(ni * 8 + lr) * BSW + ko];
                asm volatile(
                    "mma.sync.aligned.m16n8k16.row.col.f32.f16.f16.f32 "
                    "{%0,%1,%2,%3}, {%4,%5,%6,%7}, {%8,%9}, {%0,%1,%2,%3};"
                    : "+f"(acc[ni][0]), "+f"(acc[ni][1]),
                      "+f"(acc[ni][2]), "+f"(acc[ni][3])
                    : "r"(af[0]), "r"(af[1]), "r"(af[2]), "r"(af[3]),
                      "r"(b.x), "r"(b.y));
            }
        }
        const uint32_t* kp = Bb + (t >> 2) * BSW + (t & 3) * 8;
#pragma unroll
        for (int i = 0; i < 8; i++) {
            float2 f = __half22float2(*(const __half2*)&kp[i]);
            ksacc += f.x + f.y;
        }
    };

    stage(0, 0);
    for (int c = 0; c < KA_NCH; c++) {
        if (c + 1 < KA_NCH) {
            stage(c + 1, (c + 1) & 1);
            asm volatile("cp.async.wait_group 1;" ::: "memory");
        } else {
            asm volatile("cp.async.wait_group 0;" ::: "memory");
        }
        __syncthreads();
        compute(c & 1);
        __syncthreads();
    }

    float* kv = g_acc;
#pragma unroll
    for (int ni = 0; ni < 4; ni++) {
        int d  = ni * 8 + 2 * lc;
        int c0 = 16 * w + lr;
        atomicAdd(&kv[((size_t)bh * DC + c0) * DL + d],         acc[ni][0]);
        atomicAdd(&kv[((size_t)bh * DC + c0) * DL + d + 1],     acc[ni][1]);
        atomicAdd(&kv[((size_t)bh * DC + c0 + 8) * DL + d],     acc[ni][2]);
        atomicAdd(&kv[((size_t)bh * DC + c0 + 8) * DL + d + 1], acc[ni][3]);
    }
    ksacc += __shfl_xor_sync(0xffffffffu, ksacc, 1);
    ksacc += __shfl_xor_sync(0xffffffffu, ksacc, 2);
    if ((t & 3) == 0)
        atomicAdd(&g_acc[PB * PH * DC * DL + bh * DL + (t >> 2)], ksacc);
}

// ===================== output via tensor cores =====================
// grid (32 bh, 8 row-tiles), 256 threads. Per CTA: 256 q rows of one (b,h).
// C[256,72] = q[256,32] @ B[72,32]^T, B rows: 0..63 = kv[c], 64 = ksum,
// 65..71 = zero. Col 64 gives the z denominator; scale cols 0..63 by z.
#define QSW 24   // words per staged row (16 data + 8 pad; conflict-free LDS.64)

__global__ __launch_bounds__(256) void out_mma_kernel(float* __restrict__ out)
{
    __shared__ uint32_t qa[256 * QSW];   // 24576 B: q rows fp16
    __shared__ uint32_t bt[72 * QSW];    //  6912 B: [kv | ksum | 0] fp16

    const int t = threadIdx.x;
    const int bh = blockIdx.x;
    const int b = bh >> 3, h = bh & 7;
    const int grow0 = b * PM + blockIdx.y * 256;

    // stage q tile: 256 rows x 4 segs of 16B
#pragma unroll
    for (int i = 0; i < 4; i++) {
        int idx = i * 256 + t;
        int r = idx >> 2, s = idx & 3;
        asm volatile("cp.async.cg.shared.global [%0], [%1], 16;"
            :: "r"(smem_u32(qa + r * QSW + s * 4)),
               "l"(g_qp + (size_t)(grow0 + r) * PL + h * DL + s * 8));
    }
    asm volatile("cp.async.commit_group;" ::: "memory");

    // stage B tile: kv fp16 (rows 0..63)
    const float* kvg = g_acc + (size_t)bh * DC * DL;
    __half* bth = (__half*)bt;
#pragma unroll
    for (int i = 0; i < 8; i++) {
        int idx = i * 256 + t;            // n = idx>>5, d = idx&31
        int n = idx >> 5, d = idx & 31;
        bth[n * (2 * QSW) + d] = __float2half_rn(kvg[idx]);
    }
    // row 64 = ksum; rows 65..71 = 0
    if (t < 32)
        bth[64 * (2 * QSW) + t] = __float2half_rn(
            g_acc[PB * PH * DC * DL + bh * DL + t]);
    else if (t < 256) {
        int j = t - 32;
        if (j < 224) bth[(65 + (j >> 5)) * (2 * QSW) + (j & 31)] = __half(0.0f);
    }
    asm volatile("cp.async.wait_group 0;" ::: "memory");
    __syncthreads();

    const int wid = t >> 5, lane = t & 31, lr = lane >> 2, lc = lane & 3;
    const int wm = wid * 32;

    float acc[2][9][4];
#pragma unroll
    for (int mi = 0; mi < 2; mi++)
#pragma unroll
        for (int ni = 0; ni < 9; ni++)
#pragma unroll
            for (int j = 0; j < 4; j++) acc[mi][ni][j] = 0.0f;

#pragma unroll
    for (int j = 0; j < 2; j++) {        // 2 x k16 steps
        const int ko = 8 * j + 2 * lc;
        uint32_t af[2][4], bf[9][2];
#pragma unroll
        for (int mi = 0; mi < 2; mi++) {
            const int r0 = wm + mi * 16 + lr;
            uint2 lo = *(const uint2*)&qa[r0 * QSW + ko];
            uint2 hi = *(const uint2*)&qa[(r0 + 8) * QSW + ko];
            af[mi][0] = lo.x; af[mi][1] = hi.x;
            af[mi][2] = lo.y; af[mi][3] = hi.y;
        }
#pragma unroll
        for (int ni = 0; ni < 9; ni++) {
            uint2 bb = *(const uint2*)&bt[(ni * 8 + lr) * QSW + ko];
            bf[ni][0] = bb.x; bf[ni][1] = bb.y;
        }
#pragma unroll
        for (int mi = 0; mi < 2; mi++)
#pragma unroll
            for (int ni = 0; ni < 9; ni++)
                asm volatile(
                    "mma.sync.aligned.m16n8k16.row.col.f32.f16.f16.f32 "
                    "{%0,%1,%2,%3}, {%4,%5,%6,%7}, {%8,%9}, {%0,%1,%2,%3};"
                    : "+f"(acc[mi][ni][0]), "+f"(acc[mi][ni][1]),
                      "+f"(acc[mi][ni][2]), "+f"(acc[mi][ni][3])
                    : "r"(af[mi][0]), "r"(af[mi][1]),
                      "r"(af[mi][2]), "r"(af[mi][3]),
                      "r"(bf[ni][0]), "r"(bf[ni][1]));
    }

    // z from col 64 (quad leader lc=0 holds it), scale + store cols 0..63
#pragma unroll
    for (int mi = 0; mi < 2; mi++) {
        float dlo = __shfl_sync(0xffffffffu, acc[mi][8][0], lane & ~3);
        float dhi = __shfl_sync(0xffffffffu, acc[mi][8][2], lane & ~3);
        float zlo = 1.0f / (dlo + EPS);
        float zhi = 1.0f / (dhi + EPS);
        int rlo = grow0 + wm + mi * 16 + lr;
#pragma unroll
        for (int ni = 0; ni < 8; ni++) {
            int col = h * DC + ni * 8 + 2 * lc;
            float2 slo = {acc[mi][ni][0] * zlo, acc[mi][ni][1] * zlo};
            float2 shi = {acc[mi][ni][2] * zhi, acc[mi][ni][3] * zhi};
            *(float2*)&out[(size_t)rlo * PC + col]       = slo;
            *(float2*)&out[(size_t)(rlo + 8) * PC + col] = shi;
        }
    }
}

// ---------------------------------------------------------------------
extern "C" void kernel_launch(void* const* d_in, const int* in_sizes, int n_in,
                              void* d_out, int out_size)
{
    const float* input = (const float*)d_in[0];
    const float* query = (const float*)d_in[1];
    const float* Wq    = (const float*)d_in[2];
    const float* bq    = (const float*)d_in[3];
    const float* Wk    = (const float*)d_in[4];
    const float* bk    = (const float*)d_in[5];
    const float* Wv    = (const float*)d_in[6];
    const float* bv    = (const float*)d_in[7];
    float* out = (float*)d_out;
    (void)in_sizes; (void)n_in; (void)out_size;

    cudaFuncSetAttribute(kvq_gemm_kernel,
                         cudaFuncAttributeMaxDynamicSharedMemorySize, SMEM_GEMM);

    // 1) prep: weight transposes (fp16) + bias gather + zero acc
    prep_kernel<<<dim3(32, 16), dim3(32, 8)>>>(Wk, Wv, Wq, bk, bv, bq);

    // 2) combined k|v|q projection GEMM (fp32 A staged, fp16 tensor cores)
    kvq_gemm_kernel<<<1536 + 128, 256, SMEM_GEMM>>>(input, query);

    // 3) kv / ksum aggregation on tensor cores
    kv_accum_kernel<<<dim3(32, KSPLIT), 128>>>();

    // 4) output on tensor cores (z via ksum column)
    out_mma_kernel<<<dim3(32, 8), 256>>>(out);
}